// round 10
// baseline (speedup 1.0000x reference)
#include <cuda_runtime.h>
#include <cuda_bf16.h>
#include <math.h>
#include <stdint.h>

// ---------------------------------------------------------------------------
// Problem constants
// ---------------------------------------------------------------------------
namespace {
constexpr int kS = 48;          // source length
constexpr int kT = 32;          // target length
constexpr int kB = 64;          // batch
constexpr int kH = 1024;        // hidden
constexpr int kE = 512;         // embed
constexpr int kV = 32000;       // vocab
constexpr int kG = 3 * kH;      // 3072 gates
constexpr int kF = 3 * kH + kE; // 3584 out-proj features
constexpr int kXW = kE + 2*kH;  // 2560 decoder GRU input width
constexpr int kPAD = 1;
constexpr int kMR = (kT - 1) * kB; // 1984 output rows
constexpr int kMP = 2048;          // padded rows for tensor GEMM
constexpr int kME = kS * kB;       // 3072 encoder rows
}

// ---------------------------------------------------------------------------
// Packed fp32x2 helpers (FFMA2)
// ---------------------------------------------------------------------------
__device__ __forceinline__ unsigned long long pk2(float x) {
    unsigned long long r;
    unsigned u = __float_as_uint(x);
    asm("mov.b64 %0, {%1, %1};" : "=l"(r) : "r"(u));
    return r;
}
__device__ __forceinline__ void fma2(unsigned long long& d,
                                     unsigned long long a,
                                     unsigned long long b) {
    asm("fma.rn.f32x2 %0, %1, %2, %0;" : "+l"(d) : "l"(a), "l"(b));
}
__device__ __forceinline__ float lo2(unsigned long long v) {
    return __uint_as_float((unsigned)v);
}
__device__ __forceinline__ float hi2(unsigned long long v) {
    return __uint_as_float((unsigned)(v >> 32));
}

// ---------------------------------------------------------------------------
// Plain-PTX helpers: cp.async / ldmatrix / mma.sync
// ---------------------------------------------------------------------------
__device__ __forceinline__ uint32_t smem_u32(const void* p) {
    uint32_t a;
    asm("{ .reg .u64 t; cvta.to.shared.u64 t, %1; cvt.u32.u64 %0, t; }"
        : "=r"(a) : "l"(p));
    return a;
}
#define CP_ASYNC16(dst, src) \
    asm volatile("cp.async.cg.shared.global [%0], [%1], 16;" \
                 :: "r"(dst), "l"(src) : "memory")
#define CP_COMMIT() asm volatile("cp.async.commit_group;" ::: "memory")
#define CP_WAIT1()  asm volatile("cp.async.wait_group 1;" ::: "memory")
#define CP_WAIT0()  asm volatile("cp.async.wait_group 0;" ::: "memory")

__device__ __forceinline__ void ldsm4(uint32_t* r, uint32_t addr) {
    asm volatile("ldmatrix.sync.aligned.m8n8.x4.shared.b16 {%0,%1,%2,%3}, [%4];"
                 : "=r"(r[0]), "=r"(r[1]), "=r"(r[2]), "=r"(r[3])
                 : "r"(addr));
}
__device__ __forceinline__ void mma16816(float* d, const uint32_t* a,
                                         const uint32_t* b) {
    asm volatile(
        "mma.sync.aligned.m16n8k16.row.col.f32.bf16.bf16.f32 "
        "{%0,%1,%2,%3}, {%4,%5,%6,%7}, {%8,%9}, {%0,%1,%2,%3};"
        : "+f"(d[0]), "+f"(d[1]), "+f"(d[2]), "+f"(d[3])
        : "r"(a[0]), "r"(a[1]), "r"(a[2]), "r"(a[3]),
          "r"(b[0]), "r"(b[1]));
}

// ---------------------------------------------------------------------------
// Persistent scratch
// ---------------------------------------------------------------------------
__device__ float g_emb[(size_t)kME * kE];
__device__ float g_gxf[(size_t)kME * kG];
__device__ float g_gxb[(size_t)kME * kG];
__device__ float g_enc[(size_t)kME * 2 * kH];      // [b][s][2H]
__device__ float g_encproj[(size_t)kME * kH];
__device__ float g_encWi[(size_t)kME * kG];        // enc @ Wi_d[:,E:]^T
__device__ float g_h[2][2 * kB * kH];              // double-buffered h_f|h_b
__device__ float g_hcat[kB * 2 * kH];
__device__ float g_hdec[kB * kH];
__device__ float g_hp[2 * kB * kH];                // 2 K-partials
__device__ float g_ghd[2 * kB * kG];               // 2 K-partials
__device__ float g_gxet[(size_t)kMR * kG];
__device__ float g_feat[(size_t)kMR * kF];         // [h2, w, et] per step
// bf16 split operands for HMMA GEMMs
__device__ __nv_bfloat16 g_Ahi[(size_t)kMP * kF];  // decoder features
__device__ __nv_bfloat16 g_Alo[(size_t)kMP * kF];
__device__ __nv_bfloat16 g_Bhi[(size_t)kV * kF];   // W_out
__device__ __nv_bfloat16 g_Blo[(size_t)kV * kF];
__device__ __nv_bfloat16 g_Ehi[(size_t)kME * kE];  // encoder embeddings
__device__ __nv_bfloat16 g_Elo[(size_t)kME * kE];
__device__ __nv_bfloat16 g_Wifh[(size_t)kG * kE];  // Wi_f
__device__ __nv_bfloat16 g_Wifl[(size_t)kG * kE];
__device__ __nv_bfloat16 g_Wibh[(size_t)kG * kE];  // Wi_b
__device__ __nv_bfloat16 g_Wibl[(size_t)kG * kE];
__device__ __nv_bfloat16 g_Widh[(size_t)kG * kXW]; // Wi_d (full)
__device__ __nv_bfloat16 g_Widl[(size_t)kG * kXW];
__device__ __nv_bfloat16 g_Wah[(size_t)kH * kG];   // W_attn (full)
__device__ __nv_bfloat16 g_Wal[(size_t)kH * kG];
__device__ __nv_bfloat16 g_Ench[(size_t)kME * 2 * kH];
__device__ __nv_bfloat16 g_Encl[(size_t)kME * 2 * kH];

// ---------------------------------------------------------------------------
__global__ void init_kernel(float* __restrict__ out0) {
    size_t i = (size_t)blockIdx.x * blockDim.x + threadIdx.x;
    if (i < (size_t)kB * kV) out0[i] = 0.f;
    if (i < (size_t)2 * kB * kH) g_h[0][i] = 0.f;
}

// encoder embedding gather + bf16 split emit
__global__ void enc_embed_kernel(const int* __restrict__ src,
                                 const float* __restrict__ table) {
    int row = blockIdx.x;
    int tok = src[row];
    float4 v = ((const float4*)(table + (size_t)tok * kE))[threadIdx.x];
    ((float4*)(g_emb + (size_t)row * kE))[threadIdx.x] = v;
    size_t o = (size_t)row * kE + threadIdx.x * 4;
    float vv[4] = { v.x, v.y, v.z, v.w };
#pragma unroll
    for (int q = 0; q < 4; q++) {
        __nv_bfloat16 h = __float2bfloat16(vv[q]);
        g_Ehi[o + q] = h;
        g_Elo[o + q] = __float2bfloat16(vv[q] - __bfloat162float(h));
    }
}

// decoder embeddings -> feat float + bf16 split into g_Ahi/g_Alo et columns
__global__ void dec_embed_all(const int* __restrict__ trg,
                              const float* __restrict__ emb_dec) {
    int row = blockIdx.x;
    int tok = trg[row];
    float4 v = ((const float4*)(emb_dec + (size_t)tok * kE))[threadIdx.x];
    ((float4*)(g_feat + (size_t)row * kF + 3 * kH))[threadIdx.x] = v;
    size_t o = (size_t)row * kF + 3 * kH + threadIdx.x * 4;
    float vv[4] = { v.x, v.y, v.z, v.w };
#pragma unroll
    for (int q = 0; q < 4; q++) {
        __nv_bfloat16 h = __float2bfloat16(vv[q]);
        g_Ahi[o + q] = h;
        g_Alo[o + q] = __float2bfloat16(vv[q] - __bfloat162float(h));
    }
}

// ---------------------------------------------------------------------------
// bf16 split conversion (4 elements/thread, fully vectorized)
// ---------------------------------------------------------------------------
__global__ void cvt_split4(const float4* __restrict__ src,
                           __nv_bfloat162* __restrict__ hi,
                           __nv_bfloat162* __restrict__ lo, size_t n4) {
    size_t i = (size_t)blockIdx.x * blockDim.x + threadIdx.x;
    if (i >= n4) return;
    float4 v = src[i];
    __nv_bfloat16 h0 = __float2bfloat16(v.x);
    __nv_bfloat16 h1 = __float2bfloat16(v.y);
    __nv_bfloat16 h2 = __float2bfloat16(v.z);
    __nv_bfloat16 h3 = __float2bfloat16(v.w);
    hi[2 * i]     = __nv_bfloat162(h0, h1);
    hi[2 * i + 1] = __nv_bfloat162(h2, h3);
    lo[2 * i]     = __nv_bfloat162(
        __float2bfloat16(v.x - __bfloat162float(h0)),
        __float2bfloat16(v.y - __bfloat162float(h1)));
    lo[2 * i + 1] = __nv_bfloat162(
        __float2bfloat16(v.z - __bfloat162float(h2)),
        __float2bfloat16(v.w - __bfloat162float(h3)));
}

// convert feat columns [0, 3H) for 1024 rows starting at row0 (pad >= kMR)
__global__ void cvt_feat_split(int row0) {
    size_t i = (size_t)blockIdx.x * blockDim.x + threadIdx.x;
    if (i >= (size_t)1024 * (3 * kH) / 4) return;
    size_t row = row0 + i / (3 * kH / 4);
    size_t col = (i % (3 * kH / 4)) * 4;
    float4 v = make_float4(0.f, 0.f, 0.f, 0.f);
    if (row < (size_t)kMR)
        v = *(const float4*)(g_feat + row * kF + col);
    size_t o = row * kF + col;
    float vv[4] = { v.x, v.y, v.z, v.w };
#pragma unroll
    for (int q = 0; q < 4; q++) {
        __nv_bfloat16 h = __float2bfloat16(vv[q]);
        g_Ahi[o + q] = h;
        g_Alo[o + q] = __float2bfloat16(vv[q] - __bfloat162float(h));
    }
}

// ---------------------------------------------------------------------------
// Generalized HMMA GEMM (bf16x3 split, fp32 accum)
// ---------------------------------------------------------------------------
namespace outg {
constexpr int BM = 128, BN = 128, BK = 64;
constexpr int HALF = 16384;
constexpr int STAGE = 4 * HALF;
constexpr int SMEM_SZ = 2 * STAGE;          // 131072
}

__device__ __forceinline__ void hg_prefetch(
    const __nv_bfloat16* __restrict__ Ah, const __nv_bfloat16* __restrict__ Al,
    int lda,
    const __nv_bfloat16* __restrict__ Bh, const __nv_bfloat16* __restrict__ Bl,
    int ldb, int k0, uint32_t buf, int tid, int m0, int n0) {
    using namespace outg;
#pragma unroll
    for (int i = 0; i < 4; i++) {
        int id = tid + i * 256;
        int row = id >> 3, c = id & 7;
        uint32_t off = (uint32_t)(row << 7) + (c << 4);
        uint32_t sw = off ^ ((off >> 3) & 0x70);
        size_t ga = (size_t)(m0 + row) * lda + k0 + c * 8;
        size_t gb = (size_t)(n0 + row) * ldb + k0 + c * 8;
        CP_ASYNC16(buf + sw, Ah + ga);
        CP_ASYNC16(buf + HALF + sw, Al + ga);
        CP_ASYNC16(buf + 2 * HALF + sw, Bh + gb);
        CP_ASYNC16(buf + 3 * HALF + sw, Bl + gb);
    }
}

// Pass-major MMA ordering: per k-step load all fragments, then sweep the
// three split passes, each touching 16 INDEPENDENT accumulators (no RAW
// chains between consecutive mma instructions).
__device__ __forceinline__ void hg_compute(uint32_t buf, int lane,
                                           int wm, int wn,
                                           float acc[2][8][4]) {
    using namespace outg;
    const int g = lane >> 3, r = lane & 7;
#pragma unroll
    for (int ks = 0; ks < 4; ks++) {
        uint32_t ahi[2][4], alo[2][4];
#pragma unroll
        for (int mi = 0; mi < 2; mi++) {
            int row = wm + mi * 16 + ((g & 1) << 3) + r;
            int chunk = ks * 2 + (g >> 1);
            uint32_t off = (uint32_t)(row << 7) + (chunk << 4);
            uint32_t sw = off ^ ((off >> 3) & 0x70);
            ldsm4(ahi[mi], buf + sw);
            ldsm4(alo[mi], buf + HALF + sw);
        }
        uint32_t bhi[4][4], blo[4][4];
#pragma unroll
        for (int np = 0; np < 4; np++) {
            int row = wn + np * 16 + ((g >> 1) << 3) + r;
            int chunk = ks * 2 + (g & 1);
            uint32_t off = (uint32_t)(row << 7) + (chunk << 4);
            uint32_t sw = off ^ ((off >> 3) & 0x70);
            ldsm4(bhi[np], buf + 2 * HALF + sw);
            ldsm4(blo[np], buf + 3 * HALF + sw);
        }
#pragma unroll
        for (int pass = 0; pass < 3; pass++) {
            const uint32_t (*af)[4] = (pass == 2) ? alo : ahi;
            const uint32_t (*bf)[4] = (pass == 1) ? blo : bhi;
#pragma unroll
            for (int mi = 0; mi < 2; mi++) {
#pragma unroll
                for (int np = 0; np < 4; np++) {
#pragma unroll
                    for (int a = 0; a < 2; a++) {
                        mma16816(acc[mi][np * 2 + a], af[mi], &bf[np][2 * a]);
                    }
                }
            }
        }
    }
}

__global__ __launch_bounds__(256, 1)
void hgemm(const __nv_bfloat16* __restrict__ Ah,
           const __nv_bfloat16* __restrict__ Al, int lda,
           const __nv_bfloat16* __restrict__ Bh,
           const __nv_bfloat16* __restrict__ Bl, int ldb,
           const float* __restrict__ bias, float* __restrict__ C, int ldc,
           int M, int K) {
    using namespace outg;
    extern __shared__ char smem[];
    const uint32_t sb = smem_u32(smem);
    const int tid = threadIdx.x;
    const int wid = tid >> 5, lane = tid & 31;
    const int m0 = blockIdx.x * BM;
    const int n0 = blockIdx.y * BN;
    const int wm = (wid & 3) * 32;
    const int wn = (wid >> 2) * 64;
    const int nslab = K / BK;

    float acc[2][8][4];
#pragma unroll
    for (int i = 0; i < 2; i++)
#pragma unroll
        for (int j = 0; j < 8; j++)
#pragma unroll
            for (int q = 0; q < 4; q++) acc[i][j][q] = 0.f;

    hg_prefetch(Ah, Al, lda, Bh, Bl, ldb, 0, sb, tid, m0, n0);
    CP_COMMIT();
    hg_prefetch(Ah, Al, lda, Bh, Bl, ldb, BK, sb + STAGE, tid, m0, n0);
    CP_COMMIT();

    for (int s = 0; s < nslab; s++) {
        const int st = s & 1;
        if (s == nslab - 1) { CP_WAIT0(); } else { CP_WAIT1(); }
        __syncthreads();
        hg_compute(sb + st * STAGE, lane, wm, wn, acc);
        __syncthreads();
        if (s + 2 < nslab) {
            hg_prefetch(Ah, Al, lda, Bh, Bl, ldb, (s + 2) * BK,
                        sb + st * STAGE, tid, m0, n0);
            CP_COMMIT();
        }
    }

    const int r0 = m0 + wm + (lane >> 2);
    const int c0 = n0 + wn + (lane & 3) * 2;
#pragma unroll
    for (int mi = 0; mi < 2; mi++) {
#pragma unroll
        for (int ni = 0; ni < 8; ni++) {
            int row = r0 + mi * 16;
            int col = c0 + ni * 8;
            const float* d = acc[mi][ni];
            float b0 = bias ? bias[col] : 0.f;
            float b1 = bias ? bias[col + 1] : 0.f;
            if (row < M) {
                C[(size_t)row * ldc + col]     = d[0] + b0;
                C[(size_t)row * ldc + col + 1] = d[1] + b1;
            }
            if (row + 8 < M) {
                C[(size_t)(row + 8) * ldc + col]     = d[2] + b0;
                C[(size_t)(row + 8) * ldc + col + 1] = d[3] + b1;
            }
        }
    }
}

// ---------------------------------------------------------------------------
// Fused encoder recurrence step, k-lane packed FFMA2 inner loop.
// ---------------------------------------------------------------------------
__global__ __launch_bounds__(256)
void enc_step_fused(int s,
                    const float* __restrict__ Wh_f,
                    const float* __restrict__ Wh_b,
                    const float* __restrict__ bh_f,
                    const float* __restrict__ bh_b) {
    constexpr int BK = 32;
    constexpr int LDA = BK + 4;   // 36 floats = 144B rows (16B aligned)
    __shared__ __align__(16) float As[64][LDA];
    __shared__ __align__(16) float Bs[48][LDA];
    const int tid = threadIdx.x;
    const int dir = blockIdx.y;
    const int j0 = blockIdx.x * 16;
    const float* hread = g_h[s & 1] + dir * (kB * kH);
    float* hwrite = g_h[(s + 1) & 1] + dir * (kB * kH);
    const float* Wh = dir ? Wh_b : Wh_f;
    const float* bh = dir ? bh_b : bh_f;
    const float* gxbase = dir ? g_gxb : g_gxf;
    const int gpos = dir ? (kS - 1 - s) : s;

    const int tm = (tid >> 4) << 2;   // 0..60, 4 rows/thread
    const int tn = tid & 15;          // gate column within 16-wide tile

    unsigned long long acc[4][3];
#pragma unroll
    for (int i = 0; i < 4; i++)
#pragma unroll
        for (int q = 0; q < 3; q++) acc[i][q] = 0ull;

    for (int k0 = 0; k0 < kH; k0 += BK) {
#pragma unroll
        for (int h = 0; h < 2; h++) {
            int id = tid + h * 256;
            int r = id >> 3, cc = (id & 7) << 2;
            *(float4*)&As[r][cc] =
                *(const float4*)(hread + (size_t)r * kH + k0 + cc);
        }
#pragma unroll
        for (int h = 0; h < 2; h++) {
            int id = tid + h * 256;
            if (id < 384) {
                int r = id >> 3, cc = (id & 7) << 2;
                int sec = r >> 4, wi = r & 15;
                *(float4*)&Bs[r][cc] = *(const float4*)(Wh +
                    (size_t)(sec * kH + j0 + wi) * kH + k0 + cc);
            }
        }
        __syncthreads();
#pragma unroll
        for (int k = 0; k < BK; k += 2) {
            unsigned long long b0 = *(const unsigned long long*)&Bs[tn][k];
            unsigned long long b1 = *(const unsigned long long*)&Bs[16 + tn][k];
            unsigned long long b2 = *(const unsigned long long*)&Bs[32 + tn][k];
#pragma unroll
            for (int i = 0; i < 4; i++) {
                unsigned long long a =
                    *(const unsigned long long*)&As[tm + i][k];
                fma2(acc[i][0], a, b0);
                fma2(acc[i][1], a, b1);
                fma2(acc[i][2], a, b2);
            }
        }
        __syncthreads();
    }

    const int j = j0 + tn;
    const float bhr = bh[j], bhz = bh[kH + j], bhn = bh[2 * kH + j];
#pragma unroll
    for (int i = 0; i < 4; i++) {
        int b = tm + i;
        float ghr = lo2(acc[i][0]) + hi2(acc[i][0]) + bhr;
        float ghz = lo2(acc[i][1]) + hi2(acc[i][1]) + bhz;
        float ghn = lo2(acc[i][2]) + hi2(acc[i][2]) + bhn;
        const float* gx = gxbase + ((size_t)gpos * kB + b) * kG;
        float r = 1.f / (1.f + expf(-(gx[j] + ghr)));
        float z = 1.f / (1.f + expf(-(gx[kH + j] + ghz)));
        float n = tanhf(gx[2 * kH + j] + r * ghn);
        float hold = hread[(size_t)b * kH + j];
        float h2 = (1.f - z) * n + z * hold;
        hwrite[(size_t)b * kH + j] = h2;
        g_enc[((size_t)b * kS + gpos) * (2 * kH) + dir * kH + j] = h2;
    }
}

// ---------------------------------------------------------------------------
// Small-M GEMM body (FFMA2)
// ---------------------------------------------------------------------------
__device__ __forceinline__
void gemm64_body(const float* __restrict__ A, int lda,
                 const float* __restrict__ Bm, int ldb,
                 const float* __restrict__ bias,
                 float* __restrict__ C, int ldc,
                 int K, int act, int nb) {
    constexpr int BK = 32;
    __shared__ __align__(16) float As[BK][64];
    __shared__ __align__(16) float Bs[BK][64];
    const int tid = threadIdx.x;
    const int bn = nb * 64;
    const int lr = tid >> 3;
    const int lc = (tid & 7) << 2;
    const int tm = (tid >> 4) << 2;
    const int tn = (tid & 15) << 2;

    unsigned long long acc[4][2];
#pragma unroll
    for (int i = 0; i < 4; i++) { acc[i][0] = 0ull; acc[i][1] = 0ull; }

    for (int k0 = 0; k0 < K; k0 += BK) {
#pragma unroll
        for (int h = 0; h < 2; h++) {
            int r = lr + h * 32;
            float4 v = *(const float4*)(A + (size_t)r * lda + k0 + lc);
            As[lc + 0][r] = v.x; As[lc + 1][r] = v.y;
            As[lc + 2][r] = v.z; As[lc + 3][r] = v.w;
            float4 w = *(const float4*)(Bm + (size_t)(bn + r) * ldb + k0 + lc);
            Bs[lc + 0][r] = w.x; Bs[lc + 1][r] = w.y;
            Bs[lc + 2][r] = w.z; Bs[lc + 3][r] = w.w;
        }
        __syncthreads();
#pragma unroll
        for (int k = 0; k < BK; k++) {
            float4 af = *(const float4*)&As[k][tm];
            unsigned long long aa[4];
            aa[0] = pk2(af.x); aa[1] = pk2(af.y);
            aa[2] = pk2(af.z); aa[3] = pk2(af.w);
            ulonglong2 bv = *(const ulonglong2*)&Bs[k][tn];
#pragma unroll
            for (int i = 0; i < 4; i++) {
                fma2(acc[i][0], aa[i], bv.x);
                fma2(acc[i][1], aa[i], bv.y);
            }
        }
        __syncthreads();
    }
#pragma unroll
    for (int i = 0; i < 4; i++) {
        int col = bn + tn;
        float4 v;
        v.x = lo2(acc[i][0]); v.y = hi2(acc[i][0]);
        v.z = lo2(acc[i][1]); v.w = hi2(acc[i][1]);
        if (bias) {
            v.x += bias[col + 0]; v.y += bias[col + 1];
            v.z += bias[col + 2]; v.w += bias[col + 3];
        }
        if (act == 1) {
            v.x = tanhf(v.x); v.y = tanhf(v.y);
            v.z = tanhf(v.z); v.w = tanhf(v.w);
        }
        *(float4*)(C + (size_t)(tm + i) * ldc + col) = v;
    }
}

__global__ __launch_bounds__(256)
void gemm64(const float* __restrict__ A, int lda,
            const float* __restrict__ Bm, int ldb,
            const float* __restrict__ bias,
            float* __restrict__ C, int ldc, int K, int act) {
    gemm64_body(A, lda, Bm, ldb, bias, C, ldc, K, act, blockIdx.x);
}

// Decoder pre-attention GEMMs, K-split 2: hp (32 blocks) + ghd (96 blocks)
__global__ __launch_bounds__(256)
void dec_pre_gemm(const float* __restrict__ W_attn,
                  const float* __restrict__ Wh_d,
                  const float* __restrict__ bh_d) {
    int x = blockIdx.x;
    if (x < 32) {
        int ks = x >> 4, nb = x & 15;
        gemm64_body(g_hdec + ks * 512, kH, W_attn + ks * 512, kG, nullptr,
                    g_hp + (size_t)ks * kB * kH, kH, 512, 0, nb);
    } else {
        int i = x - 32;
        int ks = i / 48, nb = i % 48;
        gemm64_body(g_hdec + ks * 512, kH, Wh_d + ks * 512, kH,
                    ks == 0 ? bh_d : nullptr,
                    g_ghd + (size_t)ks * kB * kG, kG, 512, 0, nb);
    }
}

// ---------------------------------------------------------------------------
__global__ void hcat_kernel() {
    int idx = blockIdx.x * blockDim.x + threadIdx.x;
    if (idx >= 2 * kB * kH) return;
    int dir = idx / (kB * kH);
    int rem = idx - dir * (kB * kH);
    int b = rem / kH, j = rem - b * kH;
    g_hcat[(size_t)b * 2 * kH + dir * kH + j] = g_h[0][idx];
}

// ---------------------------------------------------------------------------
// Fully fused decoder step (512 threads)
// ---------------------------------------------------------------------------
__global__ __launch_bounds__(512)
void attn_step_fused(const int* __restrict__ src,
                     const float* __restrict__ v_attn,
                     const float* __restrict__ gxet_t,
                     float* __restrict__ feat_t) {
    int b = blockIdx.x;
    __shared__ float sc[kS];
    __shared__ float sgxw[kG];
    int tid = threadIdx.x, warp = tid >> 5, lane = tid & 31;
    const float* hp0 = g_hp + (size_t)b * kH;
    const float* hp1 = g_hp + (size_t)kB * kH + (size_t)b * kH;

    for (int s = warp; s < kS; s += 16) {
        const float* ep = g_encproj + ((size_t)b * kS + s) * kH;
        float p = 0.f;
        for (int j = lane; j < kH; j += 32)
            p += v_attn[j] * tanhf(hp0[j] + hp1[j] + ep[j]);
#pragma unroll
        for (int o = 16; o; o >>= 1) p += __shfl_xor_sync(0xffffffffu, p, o);
        if (lane == 0) sc[s] = (src[s * kB + b] != kPAD) ? p : -1e10f;
    }
    __syncthreads();

    if (tid < 32) {
        float v1 = sc[tid];
        float v2 = (tid + 32 < kS) ? sc[tid + 32] : -1e30f;
        float mx = fmaxf(v1, v2);
#pragma unroll
        for (int o = 16; o; o >>= 1) mx = fmaxf(mx, __shfl_xor_sync(0xffffffffu, mx, o));
        float e1 = expf(v1 - mx);
        float e2 = (tid + 32 < kS) ? expf(v2 - mx) : 0.f;
        float sm = e1 + e2;
#pragma unroll
        for (int o = 16; o; o >>= 1) sm += __shfl_xor_sync(0xffffffffu, sm, o);
        float inv = 1.f / sm;
        sc[tid] = e1 * inv;
        if (tid + 32 < kS) sc[tid + 32] = e2 * inv;
    }
    __syncthreads();

    for (int c4 = tid; c4 < 2 * kH / 4; c4 += 512) {
        float4 acc = make_float4(0.f, 0.f, 0.f, 0.f);
        const float4* base = (const float4*)(g_enc + (size_t)b * kS * 2 * kH) + c4;
#pragma unroll 8
        for (int s = 0; s < kS; s++) {
            float a = sc[s];
            float4 e = base[s * (2 * kH / 4)];
            acc.x += a * e.x; acc.y += a * e.y;
            acc.z += a * e.z; acc.w += a * e.w;
        }
        ((float4*)(feat_t + (size_t)b * kF + kH))[c4] = acc;
    }
    for (int c4 = tid; c4 < kG / 4; c4 += 512) {
        float4 acc = make_float4(0.f, 0.f, 0.f, 0.f);
        const float4* base = (const float4*)(g_encWi + (size_t)b * kS * kG) + c4;
#pragma unroll 8
        for (int s = 0; s < kS; s++) {
            float a = sc[s];
            float4 e = base[s * (kG / 4)];
            acc.x += a * e.x; acc.y += a * e.y;
            acc.z += a * e.z; acc.w += a * e.w;
        }
        *(float4*)(sgxw + c4 * 4) = acc;
    }
    __syncthreads();

    const float* q0 = g_ghd + (size_t)b * kG;
    const float* q1 = g_ghd + (size_t)kB * kG + (size_t)b * kG;
    const float* gx = gxet_t + (size_t)b * kG;
    for (int j = tid; j < kH; j += 512) {
        float h = g_hdec[(size_t)b * kH + j];
        float xr = gx[j] + sgxw[j];
        float xz = gx[kH + j] + sgxw[kH + j];
        float xn = gx[2 * kH + j] + sgxw[2 * kH + j];
        float ghr = q0[j] + q1[j];
        float ghz = q0[kH + j] + q1[kH + j];
        float ghn = q0[2 * kH + j] + q1[2 * kH + j];
        float r = 1.f / (1.f + expf(-(xr + ghr)));
        float z = 1.f / (1.f + expf(-(xz + ghz)));
        float n = tanhf(xn + r * ghn);
        float h2 = (1.f - z) * n + z * h;
        g_hdec[(size_t)b * kH + j] = h2;
        feat_t[(size_t)b * kF + j] = h2;
    }
}

// ---------------------------------------------------------------------------
// Host orchestration (two-stream fork/join, graph-capturable)
// ---------------------------------------------------------------------------
extern "C" void kernel_launch(void* const* d_in, const int* in_sizes, int n_in,
                              void* d_out, int out_size) {
    const int*   src     = (const int*)d_in[0];
    const int*   trg     = (const int*)d_in[1];
    const float* emb_enc = (const float*)d_in[2];
    const float* Wi_f    = (const float*)d_in[3];
    const float* Wh_f    = (const float*)d_in[4];
    const float* bi_f    = (const float*)d_in[5];
    const float* bh_f    = (const float*)d_in[6];
    const float* Wi_b    = (const float*)d_in[7];
    const float* Wh_b    = (const float*)d_in[8];
    const float* bi_b    = (const float*)d_in[9];
    const float* bh_b    = (const float*)d_in[10];
    const float* W_fc    = (const float*)d_in[11];
    const float* b_fc    = (const float*)d_in[12];
    const float* W_attn  = (const float*)d_in[13];
    const float* b_attn  = (const float*)d_in[14];
    const float* v_attn  = (const float*)d_in[15];
    const float* emb_dec = (const float*)d_in[16];
    const float* Wi_d    = (const float*)d_in[17];
    const float* Wh_d    = (const float*)d_in[18];
    const float* bi_d    = (const float*)d_in[19];
    const float* bh_d    = (const float*)d_in[20];
    const float* W_out   = (const float*)d_in[21];
    const float* b_out   = (const float*)d_in[22];
    float* out = (float*)d_out;

    float *p_enc, *p_ep, *p_encWi, *p_hcat, *p_hdec, *p_gxet, *p_feat,
          *p_gxf, *p_gxb;
    __nv_bfloat16 *p_Ahi, *p_Alo, *p_Bhi, *p_Blo, *p_Ehi, *p_Elo;
    __nv_bfloat16 *p_Wifh, *p_Wifl, *p_Wibh, *p_Wibl;
    __nv_bfloat16 *p_Widh, *p_Widl, *p_Wah, *p_Wal, *p_Ench, *p_Encl;
    cudaGetSymbolAddress((void**)&p_enc, g_enc);
    cudaGetSymbolAddress((void**)&p_ep, g_encproj);
    cudaGetSymbolAddress((void**)&p_encWi, g_encWi);
    cudaGetSymbolAddress((void**)&p_hcat, g_hcat);
    cudaGetSymbolAddress((void**)&p_hdec, g_hdec);
    cudaGetSymbolAddress((void**)&p_gxet, g_gxet);
    cudaGetSymbolAddress((void**)&p_feat, g_feat);
    cudaGetSymbolAddress((void**)&p_gxf, g_gxf);
    cudaGetSymbolAddress((void**)&p_gxb, g_gxb);
    cudaGetSymbolAddress((void**)&p_Ahi, g_Ahi);
    cudaGetSymbolAddress((void**)&p_Alo, g_Alo);
    cudaGetSymbolAddress((void**)&p_Bhi, g_Bhi);
    cudaGetSymbolAddress((void**)&p_Blo, g_Blo);
    cudaGetSymbolAddress((void**)&p_Ehi, g_Ehi);
    cudaGetSymbolAddress((void**)&p_Elo, g_Elo);
    cudaGetSymbolAddress((void**)&p_Wifh, g_Wifh);
    cudaGetSymbolAddress((void**)&p_Wifl, g_Wifl);
    cudaGetSymbolAddress((void**)&p_Wibh, g_Wibh);
    cudaGetSymbolAddress((void**)&p_Wibl, g_Wibl);
    cudaGetSymbolAddress((void**)&p_Widh, g_Widh);
    cudaGetSymbolAddress((void**)&p_Widl, g_Widl);
    cudaGetSymbolAddress((void**)&p_Wah, g_Wah);
    cudaGetSymbolAddress((void**)&p_Wal, g_Wal);
    cudaGetSymbolAddress((void**)&p_Ench, g_Ench);
    cudaGetSymbolAddress((void**)&p_Encl, g_Encl);

    static cudaStream_t s1 = nullptr;
    static cudaEvent_t evFork = nullptr, evJoin = nullptr;
    static cudaEvent_t evFork2 = nullptr, evJoin2 = nullptr;
    if (s1 == nullptr) {
        cudaStreamCreateWithFlags(&s1, cudaStreamNonBlocking);
        cudaEventCreateWithFlags(&evFork, cudaEventDisableTiming);
        cudaEventCreateWithFlags(&evJoin, cudaEventDisableTiming);
        cudaEventCreateWithFlags(&evFork2, cudaEventDisableTiming);
        cudaEventCreateWithFlags(&evJoin2, cudaEventDisableTiming);
        cudaFuncSetAttribute(hgemm,
                             cudaFuncAttributeMaxDynamicSharedMemorySize,
                             outg::SMEM_SZ);
    }

    // fork side stream off the capture stream
    cudaEventRecord(evFork, 0);
    cudaStreamWaitEvent(s1, evFork, 0);

    // --- main stream: encoder-critical path ---
    init_kernel<<<((size_t)kB * kV + 255) / 256, 256>>>(out);
    enc_embed_kernel<<<kME, 128>>>(src, emb_enc);
    {
        size_t n4 = (size_t)kG * kE / 4;
        cvt_split4<<<(unsigned)((n4 + 255) / 256), 256>>>(
            (const float4*)Wi_f, (__nv_bfloat162*)p_Wifh,
            (__nv_bfloat162*)p_Wifl, n4);
        cvt_split4<<<(unsigned)((n4 + 255) / 256), 256>>>(
            (const float4*)Wi_b, (__nv_bfloat162*)p_Wibh,
            (__nv_bfloat162*)p_Wibl, n4);
    }
    // --- side stream: decoder-prep + big weight conversions ---
    dec_embed_all<<<kMR, 128, 0, s1>>>(trg, emb_dec);
    // --- main: input-gate GEMMs ---
    hgemm<<<dim3(kME / 128, kG / 128), 256, outg::SMEM_SZ>>>(
        p_Ehi, p_Elo, kE, p_Wifh, p_Wifl, kE, bi_f, p_gxf, kG, kME, kE);
    hgemm<<<dim3(kME / 128, kG / 128), 256, outg::SMEM_SZ>>>(
        p_Ehi, p_Elo, kE, p_Wibh, p_Wibl, kE, bi_b, p_gxb, kG, kME, kE);
    // --- side stream continues ---
    {
        size_t n4 = (size_t)kG * kXW / 4;
        cvt_split4<<<(unsigned)((n4 + 255) / 256), 256, 0, s1>>>(
            (const float4*)Wi_d, (__nv_bfloat162*)p_Widh,
            (__nv_bfloat162*)p_Widl, n4);
        n4 = (size_t)kH * kG / 4;
        cvt_split4<<<(unsigned)((n4 + 255) / 256), 256, 0, s1>>>(
            (const float4*)W_attn, (__nv_bfloat162*)p_Wah,
            (__nv_bfloat162*)p_Wal, n4);
        hgemm<<<dim3(kMP / 128, kG / 128), 256, outg::SMEM_SZ, s1>>>(
            p_Ahi + 3 * kH, p_Alo + 3 * kH, kF, p_Widh, p_Widl, kXW, bi_d,
            p_gxet, kG, kMR, kE);
        n4 = (size_t)kV * kF / 4;
        cvt_split4<<<(unsigned)((n4 + 255) / 256), 256, 0, s1>>>(
            (const float4*)W_out, (__nv_bfloat162*)p_Bhi,
            (__nv_bfloat162*)p_Blo, n4);
    }
    cudaEventRecord(evJoin, s1);

    // --- main: encoder recurrence (overlaps side stream) ---
    for (int s = 0; s < kS; s++)
        enc_step_fused<<<dim3(64, 2), 256>>>(s, Wh_f, Wh_b, bh_f, bh_b);

    // decoder init hidden
    hcat_kernel<<<(2 * kB * kH) / 256, 256>>>();
    gemm64<<<kH / 64, 256>>>(p_hcat, 2 * kH, W_fc, 2 * kH, b_fc,
                             p_hdec, kH, 2 * kH, 1);

    // encoder split + attention projection + encWi (needs side stream)
    {
        size_t n4 = (size_t)kME * 2 * kH / 4;
        cvt_split4<<<(unsigned)((n4 + 255) / 256), 256>>>(
            (const float4*)p_enc, (__nv_bfloat162*)p_Ench,
            (__nv_bfloat162*)p_Encl, n4);
        cudaStreamWaitEvent(0, evJoin, 0);
        hgemm<<<dim3(kME / 128, kH / 128), 256, outg::SMEM_SZ>>>(
            p_Ench, p_Encl, 2 * kH, p_Wah + kH, p_Wal + kH, kG, b_attn,
            p_ep, kH, kME, 2 * kH);
        hgemm<<<dim3(kME / 128, kG / 128), 256, outg::SMEM_SZ>>>(
            p_Ench, p_Encl, 2 * kH, p_Widh + kE, p_Widl + kE, kXW,
            (const float*)nullptr, p_encWi, kG, kME, 2 * kH);
    }

    // decoder loop: 2 launches per step; after t=15 the first 1024 feat
    // rows are final -> overlap first half of the output GEMM on s1.
    for (int t = 0; t < kT - 1; t++) {
        float* feat_t = p_feat + (size_t)t * kB * kF;
        dec_pre_gemm<<<128, 256>>>(W_attn, Wh_d, bh_d);
        attn_step_fused<<<kB, 512>>>(src, v_attn,
                                     p_gxet + (size_t)t * kB * kG, feat_t);
        if (t == 15) {
            cudaEventRecord(evFork2, 0);
            cudaStreamWaitEvent(s1, evFork2, 0);
            cvt_feat_split<<<3072, 256, 0, s1>>>(0);
            hgemm<<<dim3(8, kV / 128), 256, outg::SMEM_SZ, s1>>>(
                p_Ahi, p_Alo, kF, p_Bhi, p_Blo, kF, b_out,
                out + (size_t)kB * kV, kV, 1024, kF);
            cudaEventRecord(evJoin2, s1);
        }
    }

    // second half of the output projection on the main stream
    cvt_feat_split<<<3072, 256>>>(1024);
    hgemm<<<dim3(8, kV / 128), 256, outg::SMEM_SZ>>>(
        p_Ahi + (size_t)1024 * kF, p_Alo + (size_t)1024 * kF, kF,
        p_Bhi, p_Blo, kF, b_out,
        out + (size_t)kB * kV + (size_t)1024 * kV, kV, kMR - 1024, kF);
    cudaStreamWaitEvent(0, evJoin2, 0);
}

// round 11
// speedup vs baseline: 1.0109x; 1.0109x over previous
#include <cuda_runtime.h>
#include <cuda_bf16.h>
#include <math.h>
#include <stdint.h>

// ---------------------------------------------------------------------------
// Problem constants
// ---------------------------------------------------------------------------
namespace {
constexpr int kS = 48;          // source length
constexpr int kT = 32;          // target length
constexpr int kB = 64;          // batch
constexpr int kH = 1024;        // hidden
constexpr int kE = 512;         // embed
constexpr int kV = 32000;       // vocab
constexpr int kG = 3 * kH;      // 3072 gates
constexpr int kF = 3 * kH + kE; // 3584 out-proj features
constexpr int kXW = kE + 2*kH;  // 2560 decoder GRU input width
constexpr int kPAD = 1;
constexpr int kMR = (kT - 1) * kB; // 1984 output rows
constexpr int kMP = 2048;          // padded rows for tensor GEMM
constexpr int kME = kS * kB;       // 3072 encoder rows
}

// ---------------------------------------------------------------------------
// Packed fp32x2 helpers (FFMA2)
// ---------------------------------------------------------------------------
__device__ __forceinline__ unsigned long long pk2(float x) {
    unsigned long long r;
    unsigned u = __float_as_uint(x);
    asm("mov.b64 %0, {%1, %1};" : "=l"(r) : "r"(u));
    return r;
}
__device__ __forceinline__ void fma2(unsigned long long& d,
                                     unsigned long long a,
                                     unsigned long long b) {
    asm("fma.rn.f32x2 %0, %1, %2, %0;" : "+l"(d) : "l"(a), "l"(b));
}
__device__ __forceinline__ float lo2(unsigned long long v) {
    return __uint_as_float((unsigned)v);
}
__device__ __forceinline__ float hi2(unsigned long long v) {
    return __uint_as_float((unsigned)(v >> 32));
}

// ---------------------------------------------------------------------------
// Plain-PTX helpers: cp.async / ldmatrix / mma.sync
// ---------------------------------------------------------------------------
__device__ __forceinline__ uint32_t smem_u32(const void* p) {
    uint32_t a;
    asm("{ .reg .u64 t; cvta.to.shared.u64 t, %1; cvt.u32.u64 %0, t; }"
        : "=r"(a) : "l"(p));
    return a;
}
#define CP_ASYNC16(dst, src) \
    asm volatile("cp.async.cg.shared.global [%0], [%1], 16;" \
                 :: "r"(dst), "l"(src) : "memory")
#define CP_COMMIT() asm volatile("cp.async.commit_group;" ::: "memory")
#define CP_WAIT1()  asm volatile("cp.async.wait_group 1;" ::: "memory")
#define CP_WAIT0()  asm volatile("cp.async.wait_group 0;" ::: "memory")

__device__ __forceinline__ void ldsm4(uint32_t* r, uint32_t addr) {
    asm volatile("ldmatrix.sync.aligned.m8n8.x4.shared.b16 {%0,%1,%2,%3}, [%4];"
                 : "=r"(r[0]), "=r"(r[1]), "=r"(r[2]), "=r"(r[3])
                 : "r"(addr));
}
__device__ __forceinline__ void mma16816(float* d, const uint32_t* a,
                                         const uint32_t* b) {
    asm volatile(
        "mma.sync.aligned.m16n8k16.row.col.f32.bf16.bf16.f32 "
        "{%0,%1,%2,%3}, {%4,%5,%6,%7}, {%8,%9}, {%0,%1,%2,%3};"
        : "+f"(d[0]), "+f"(d[1]), "+f"(d[2]), "+f"(d[3])
        : "r"(a[0]), "r"(a[1]), "r"(a[2]), "r"(a[3]),
          "r"(b[0]), "r"(b[1]));
}

// ---------------------------------------------------------------------------
// Persistent scratch
// ---------------------------------------------------------------------------
__device__ float g_emb[(size_t)kME * kE];
__device__ float g_gxf[(size_t)kME * kG];
__device__ float g_gxb[(size_t)kME * kG];
__device__ float g_enc[(size_t)kME * 2 * kH];      // [b][s][2H]
__device__ float g_encproj[(size_t)kME * kH];
__device__ float g_encWi[(size_t)kME * kG];        // enc @ Wi_d[:,E:]^T
__device__ float g_h[2][2 * kB * kH];              // double-buffered h_f|h_b
__device__ float g_hcat[kB * 2 * kH];
__device__ float g_hdec[kB * kH];
__device__ float g_hp[2 * kB * kH];                // 2 K-partials
__device__ float g_ghd[2 * kB * kG];               // 2 K-partials
__device__ float g_gxet[(size_t)kMR * kG];
__device__ float g_feat[(size_t)kMR * kF];         // [h2, w, et] per step
// bf16 split operands for HMMA GEMMs
__device__ __nv_bfloat16 g_Ahi[(size_t)kMP * kF];  // decoder features
__device__ __nv_bfloat16 g_Alo[(size_t)kMP * kF];
__device__ __nv_bfloat16 g_Bhi[(size_t)kV * kF];   // W_out
__device__ __nv_bfloat16 g_Blo[(size_t)kV * kF];
__device__ __nv_bfloat16 g_Ehi[(size_t)kME * kE];  // encoder embeddings
__device__ __nv_bfloat16 g_Elo[(size_t)kME * kE];
__device__ __nv_bfloat16 g_Wifh[(size_t)kG * kE];  // Wi_f
__device__ __nv_bfloat16 g_Wifl[(size_t)kG * kE];
__device__ __nv_bfloat16 g_Wibh[(size_t)kG * kE];  // Wi_b
__device__ __nv_bfloat16 g_Wibl[(size_t)kG * kE];
__device__ __nv_bfloat16 g_Widh[(size_t)kG * kXW]; // Wi_d (full)
__device__ __nv_bfloat16 g_Widl[(size_t)kG * kXW];
__device__ __nv_bfloat16 g_Wah[(size_t)kH * kG];   // W_attn (full)
__device__ __nv_bfloat16 g_Wal[(size_t)kH * kG];
__device__ __nv_bfloat16 g_Ench[(size_t)kME * 2 * kH];
__device__ __nv_bfloat16 g_Encl[(size_t)kME * 2 * kH];

// ---------------------------------------------------------------------------
__global__ void init_kernel(float* __restrict__ out0) {
    size_t i = (size_t)blockIdx.x * blockDim.x + threadIdx.x;
    if (i < (size_t)kB * kV) out0[i] = 0.f;
    if (i < (size_t)2 * kB * kH) g_h[0][i] = 0.f;
}

// encoder embedding gather + bf16 split emit
__global__ void enc_embed_kernel(const int* __restrict__ src,
                                 const float* __restrict__ table) {
    int row = blockIdx.x;
    int tok = src[row];
    float4 v = ((const float4*)(table + (size_t)tok * kE))[threadIdx.x];
    ((float4*)(g_emb + (size_t)row * kE))[threadIdx.x] = v;
    size_t o = (size_t)row * kE + threadIdx.x * 4;
    float vv[4] = { v.x, v.y, v.z, v.w };
#pragma unroll
    for (int q = 0; q < 4; q++) {
        __nv_bfloat16 h = __float2bfloat16(vv[q]);
        g_Ehi[o + q] = h;
        g_Elo[o + q] = __float2bfloat16(vv[q] - __bfloat162float(h));
    }
}

// decoder embeddings -> feat float + bf16 split into g_Ahi/g_Alo et columns
__global__ void dec_embed_all(const int* __restrict__ trg,
                              const float* __restrict__ emb_dec) {
    int row = blockIdx.x;
    int tok = trg[row];
    float4 v = ((const float4*)(emb_dec + (size_t)tok * kE))[threadIdx.x];
    ((float4*)(g_feat + (size_t)row * kF + 3 * kH))[threadIdx.x] = v;
    size_t o = (size_t)row * kF + 3 * kH + threadIdx.x * 4;
    float vv[4] = { v.x, v.y, v.z, v.w };
#pragma unroll
    for (int q = 0; q < 4; q++) {
        __nv_bfloat16 h = __float2bfloat16(vv[q]);
        g_Ahi[o + q] = h;
        g_Alo[o + q] = __float2bfloat16(vv[q] - __bfloat162float(h));
    }
}

// ---------------------------------------------------------------------------
// bf16 split conversion (4 elements/thread, fully vectorized)
// ---------------------------------------------------------------------------
__global__ void cvt_split4(const float4* __restrict__ src,
                           __nv_bfloat162* __restrict__ hi,
                           __nv_bfloat162* __restrict__ lo, size_t n4) {
    size_t i = (size_t)blockIdx.x * blockDim.x + threadIdx.x;
    if (i >= n4) return;
    float4 v = src[i];
    __nv_bfloat16 h0 = __float2bfloat16(v.x);
    __nv_bfloat16 h1 = __float2bfloat16(v.y);
    __nv_bfloat16 h2 = __float2bfloat16(v.z);
    __nv_bfloat16 h3 = __float2bfloat16(v.w);
    hi[2 * i]     = __nv_bfloat162(h0, h1);
    hi[2 * i + 1] = __nv_bfloat162(h2, h3);
    lo[2 * i]     = __nv_bfloat162(
        __float2bfloat16(v.x - __bfloat162float(h0)),
        __float2bfloat16(v.y - __bfloat162float(h1)));
    lo[2 * i + 1] = __nv_bfloat162(
        __float2bfloat16(v.z - __bfloat162float(h2)),
        __float2bfloat16(v.w - __bfloat162float(h3)));
}

// convert feat columns [0, 3H) for all padded rows
__global__ void cvt_feat_split() {
    size_t i = (size_t)blockIdx.x * blockDim.x + threadIdx.x;
    if (i >= (size_t)kMP * (3 * kH) / 4) return;
    size_t row = i / (3 * kH / 4);
    size_t col = (i % (3 * kH / 4)) * 4;
    float4 v = make_float4(0.f, 0.f, 0.f, 0.f);
    if (row < (size_t)kMR)
        v = *(const float4*)(g_feat + row * kF + col);
    size_t o = row * kF + col;
    float vv[4] = { v.x, v.y, v.z, v.w };
#pragma unroll
    for (int q = 0; q < 4; q++) {
        __nv_bfloat16 h = __float2bfloat16(vv[q]);
        g_Ahi[o + q] = h;
        g_Alo[o + q] = __float2bfloat16(vv[q] - __bfloat162float(h));
    }
}

// ---------------------------------------------------------------------------
// Generalized HMMA GEMM (bf16x3 split, fp32 accum)
// ---------------------------------------------------------------------------
namespace outg {
constexpr int BM = 128, BN = 128, BK = 64;
constexpr int HALF = 16384;
constexpr int STAGE = 4 * HALF;
constexpr int SMEM_SZ = 2 * STAGE;          // 131072
}

__device__ __forceinline__ void hg_prefetch(
    const __nv_bfloat16* __restrict__ Ah, const __nv_bfloat16* __restrict__ Al,
    int lda,
    const __nv_bfloat16* __restrict__ Bh, const __nv_bfloat16* __restrict__ Bl,
    int ldb, int k0, uint32_t buf, int tid, int m0, int n0) {
    using namespace outg;
#pragma unroll
    for (int i = 0; i < 4; i++) {
        int id = tid + i * 256;
        int row = id >> 3, c = id & 7;
        uint32_t off = (uint32_t)(row << 7) + (c << 4);
        uint32_t sw = off ^ ((off >> 3) & 0x70);
        size_t ga = (size_t)(m0 + row) * lda + k0 + c * 8;
        size_t gb = (size_t)(n0 + row) * ldb + k0 + c * 8;
        CP_ASYNC16(buf + sw, Ah + ga);
        CP_ASYNC16(buf + HALF + sw, Al + ga);
        CP_ASYNC16(buf + 2 * HALF + sw, Bh + gb);
        CP_ASYNC16(buf + 3 * HALF + sw, Bl + gb);
    }
}

// Pass-major MMA ordering: per k-step load all fragments, then sweep the
// three split passes, each touching 16 INDEPENDENT accumulators.
__device__ __forceinline__ void hg_compute(uint32_t buf, int lane,
                                           int wm, int wn,
                                           float acc[2][8][4]) {
    using namespace outg;
    const int g = lane >> 3, r = lane & 7;
#pragma unroll
    for (int ks = 0; ks < 4; ks++) {
        uint32_t ahi[2][4], alo[2][4];
#pragma unroll
        for (int mi = 0; mi < 2; mi++) {
            int row = wm + mi * 16 + ((g & 1) << 3) + r;
            int chunk = ks * 2 + (g >> 1);
            uint32_t off = (uint32_t)(row << 7) + (chunk << 4);
            uint32_t sw = off ^ ((off >> 3) & 0x70);
            ldsm4(ahi[mi], buf + sw);
            ldsm4(alo[mi], buf + HALF + sw);
        }
        uint32_t bhi[4][4], blo[4][4];
#pragma unroll
        for (int np = 0; np < 4; np++) {
            int row = wn + np * 16 + ((g >> 1) << 3) + r;
            int chunk = ks * 2 + (g & 1);
            uint32_t off = (uint32_t)(row << 7) + (chunk << 4);
            uint32_t sw = off ^ ((off >> 3) & 0x70);
            ldsm4(bhi[np], buf + 2 * HALF + sw);
            ldsm4(blo[np], buf + 3 * HALF + sw);
        }
#pragma unroll
        for (int pass = 0; pass < 3; pass++) {
            const uint32_t (*af)[4] = (pass == 2) ? alo : ahi;
            const uint32_t (*bf)[4] = (pass == 1) ? blo : bhi;
#pragma unroll
            for (int mi = 0; mi < 2; mi++) {
#pragma unroll
                for (int np = 0; np < 4; np++) {
#pragma unroll
                    for (int a = 0; a < 2; a++) {
                        mma16816(acc[mi][np * 2 + a], af[mi], &bf[np][2 * a]);
                    }
                }
            }
        }
    }
}

__global__ __launch_bounds__(256, 1)
void hgemm(const __nv_bfloat16* __restrict__ Ah,
           const __nv_bfloat16* __restrict__ Al, int lda,
           const __nv_bfloat16* __restrict__ Bh,
           const __nv_bfloat16* __restrict__ Bl, int ldb,
           const float* __restrict__ bias, float* __restrict__ C, int ldc,
           int M, int K) {
    using namespace outg;
    extern __shared__ char smem[];
    const uint32_t sb = smem_u32(smem);
    const int tid = threadIdx.x;
    const int wid = tid >> 5, lane = tid & 31;
    const int m0 = blockIdx.x * BM;
    const int n0 = blockIdx.y * BN;
    const int wm = (wid & 3) * 32;
    const int wn = (wid >> 2) * 64;
    const int nslab = K / BK;

    float acc[2][8][4];
#pragma unroll
    for (int i = 0; i < 2; i++)
#pragma unroll
        for (int j = 0; j < 8; j++)
#pragma unroll
            for (int q = 0; q < 4; q++) acc[i][j][q] = 0.f;

    hg_prefetch(Ah, Al, lda, Bh, Bl, ldb, 0, sb, tid, m0, n0);
    CP_COMMIT();
    hg_prefetch(Ah, Al, lda, Bh, Bl, ldb, BK, sb + STAGE, tid, m0, n0);
    CP_COMMIT();

    for (int s = 0; s < nslab; s++) {
        const int st = s & 1;
        if (s == nslab - 1) { CP_WAIT0(); } else { CP_WAIT1(); }
        __syncthreads();
        hg_compute(sb + st * STAGE, lane, wm, wn, acc);
        __syncthreads();
        if (s + 2 < nslab) {
            hg_prefetch(Ah, Al, lda, Bh, Bl, ldb, (s + 2) * BK,
                        sb + st * STAGE, tid, m0, n0);
            CP_COMMIT();
        }
    }

    const int r0 = m0 + wm + (lane >> 2);
    const int c0 = n0 + wn + (lane & 3) * 2;
#pragma unroll
    for (int mi = 0; mi < 2; mi++) {
#pragma unroll
        for (int ni = 0; ni < 8; ni++) {
            int row = r0 + mi * 16;
            int col = c0 + ni * 8;
            const float* d = acc[mi][ni];
            float b0 = bias ? bias[col] : 0.f;
            float b1 = bias ? bias[col + 1] : 0.f;
            if (row < M) {
                C[(size_t)row * ldc + col]     = d[0] + b0;
                C[(size_t)row * ldc + col + 1] = d[1] + b1;
            }
            if (row + 8 < M) {
                C[(size_t)(row + 8) * ldc + col]     = d[2] + b0;
                C[(size_t)(row + 8) * ldc + col + 1] = d[3] + b1;
            }
        }
    }
}

// ---------------------------------------------------------------------------
// Fused encoder recurrence step, k-lane packed FFMA2 inner loop.
// ---------------------------------------------------------------------------
__global__ __launch_bounds__(256)
void enc_step_fused(int s,
                    const float* __restrict__ Wh_f,
                    const float* __restrict__ Wh_b,
                    const float* __restrict__ bh_f,
                    const float* __restrict__ bh_b) {
    constexpr int BK = 32;
    constexpr int LDA = BK + 4;   // 36 floats = 144B rows (16B aligned)
    __shared__ __align__(16) float As[64][LDA];
    __shared__ __align__(16) float Bs[48][LDA];
    const int tid = threadIdx.x;
    const int dir = blockIdx.y;
    const int j0 = blockIdx.x * 16;
    const float* hread = g_h[s & 1] + dir * (kB * kH);
    float* hwrite = g_h[(s + 1) & 1] + dir * (kB * kH);
    const float* Wh = dir ? Wh_b : Wh_f;
    const float* bh = dir ? bh_b : bh_f;
    const float* gxbase = dir ? g_gxb : g_gxf;
    const int gpos = dir ? (kS - 1 - s) : s;

    const int tm = (tid >> 4) << 2;   // 0..60, 4 rows/thread
    const int tn = tid & 15;          // gate column within 16-wide tile

    unsigned long long acc[4][3];
#pragma unroll
    for (int i = 0; i < 4; i++)
#pragma unroll
        for (int q = 0; q < 3; q++) acc[i][q] = 0ull;

    for (int k0 = 0; k0 < kH; k0 += BK) {
#pragma unroll
        for (int h = 0; h < 2; h++) {
            int id = tid + h * 256;
            int r = id >> 3, cc = (id & 7) << 2;
            *(float4*)&As[r][cc] =
                *(const float4*)(hread + (size_t)r * kH + k0 + cc);
        }
#pragma unroll
        for (int h = 0; h < 2; h++) {
            int id = tid + h * 256;
            if (id < 384) {
                int r = id >> 3, cc = (id & 7) << 2;
                int sec = r >> 4, wi = r & 15;
                *(float4*)&Bs[r][cc] = *(const float4*)(Wh +
                    (size_t)(sec * kH + j0 + wi) * kH + k0 + cc);
            }
        }
        __syncthreads();
#pragma unroll
        for (int k = 0; k < BK; k += 2) {
            unsigned long long b0 = *(const unsigned long long*)&Bs[tn][k];
            unsigned long long b1 = *(const unsigned long long*)&Bs[16 + tn][k];
            unsigned long long b2 = *(const unsigned long long*)&Bs[32 + tn][k];
#pragma unroll
            for (int i = 0; i < 4; i++) {
                unsigned long long a =
                    *(const unsigned long long*)&As[tm + i][k];
                fma2(acc[i][0], a, b0);
                fma2(acc[i][1], a, b1);
                fma2(acc[i][2], a, b2);
            }
        }
        __syncthreads();
    }

    const int j = j0 + tn;
    const float bhr = bh[j], bhz = bh[kH + j], bhn = bh[2 * kH + j];
#pragma unroll
    for (int i = 0; i < 4; i++) {
        int b = tm + i;
        float ghr = lo2(acc[i][0]) + hi2(acc[i][0]) + bhr;
        float ghz = lo2(acc[i][1]) + hi2(acc[i][1]) + bhz;
        float ghn = lo2(acc[i][2]) + hi2(acc[i][2]) + bhn;
        const float* gx = gxbase + ((size_t)gpos * kB + b) * kG;
        float r = 1.f / (1.f + expf(-(gx[j] + ghr)));
        float z = 1.f / (1.f + expf(-(gx[kH + j] + ghz)));
        float n = tanhf(gx[2 * kH + j] + r * ghn);
        float hold = hread[(size_t)b * kH + j];
        float h2 = (1.f - z) * n + z * hold;
        hwrite[(size_t)b * kH + j] = h2;
        g_enc[((size_t)b * kS + gpos) * (2 * kH) + dir * kH + j] = h2;
    }
}

// ---------------------------------------------------------------------------
// Small-M GEMM body (FFMA2)
// ---------------------------------------------------------------------------
__device__ __forceinline__
void gemm64_body(const float* __restrict__ A, int lda,
                 const float* __restrict__ Bm, int ldb,
                 const float* __restrict__ bias,
                 float* __restrict__ C, int ldc,
                 int K, int act, int nb) {
    constexpr int BK = 32;
    __shared__ __align__(16) float As[BK][64];
    __shared__ __align__(16) float Bs[BK][64];
    const int tid = threadIdx.x;
    const int bn = nb * 64;
    const int lr = tid >> 3;
    const int lc = (tid & 7) << 2;
    const int tm = (tid >> 4) << 2;
    const int tn = (tid & 15) << 2;

    unsigned long long acc[4][2];
#pragma unroll
    for (int i = 0; i < 4; i++) { acc[i][0] = 0ull; acc[i][1] = 0ull; }

    for (int k0 = 0; k0 < K; k0 += BK) {
#pragma unroll
        for (int h = 0; h < 2; h++) {
            int r = lr + h * 32;
            float4 v = *(const float4*)(A + (size_t)r * lda + k0 + lc);
            As[lc + 0][r] = v.x; As[lc + 1][r] = v.y;
            As[lc + 2][r] = v.z; As[lc + 3][r] = v.w;
            float4 w = *(const float4*)(Bm + (size_t)(bn + r) * ldb + k0 + lc);
            Bs[lc + 0][r] = w.x; Bs[lc + 1][r] = w.y;
            Bs[lc + 2][r] = w.z; Bs[lc + 3][r] = w.w;
        }
        __syncthreads();
#pragma unroll
        for (int k = 0; k < BK; k++) {
            float4 af = *(const float4*)&As[k][tm];
            unsigned long long aa[4];
            aa[0] = pk2(af.x); aa[1] = pk2(af.y);
            aa[2] = pk2(af.z); aa[3] = pk2(af.w);
            ulonglong2 bv = *(const ulonglong2*)&Bs[k][tn];
#pragma unroll
            for (int i = 0; i < 4; i++) {
                fma2(acc[i][0], aa[i], bv.x);
                fma2(acc[i][1], aa[i], bv.y);
            }
        }
        __syncthreads();
    }
#pragma unroll
    for (int i = 0; i < 4; i++) {
        int col = bn + tn;
        float4 v;
        v.x = lo2(acc[i][0]); v.y = hi2(acc[i][0]);
        v.z = lo2(acc[i][1]); v.w = hi2(acc[i][1]);
        if (bias) {
            v.x += bias[col + 0]; v.y += bias[col + 1];
            v.z += bias[col + 2]; v.w += bias[col + 3];
        }
        if (act == 1) {
            v.x = tanhf(v.x); v.y = tanhf(v.y);
            v.z = tanhf(v.z); v.w = tanhf(v.w);
        }
        *(float4*)(C + (size_t)(tm + i) * ldc + col) = v;
    }
}

__global__ __launch_bounds__(256)
void gemm64(const float* __restrict__ A, int lda,
            const float* __restrict__ Bm, int ldb,
            const float* __restrict__ bias,
            float* __restrict__ C, int ldc, int K, int act) {
    gemm64_body(A, lda, Bm, ldb, bias, C, ldc, K, act, blockIdx.x);
}

// Decoder pre-attention GEMMs, K-split 2: hp (32 blocks) + ghd (96 blocks)
__global__ __launch_bounds__(256)
void dec_pre_gemm(const float* __restrict__ W_attn,
                  const float* __restrict__ Wh_d,
                  const float* __restrict__ bh_d) {
    int x = blockIdx.x;
    if (x < 32) {
        int ks = x >> 4, nb = x & 15;
        gemm64_body(g_hdec + ks * 512, kH, W_attn + ks * 512, kG, nullptr,
                    g_hp + (size_t)ks * kB * kH, kH, 512, 0, nb);
    } else {
        int i = x - 32;
        int ks = i / 48, nb = i % 48;
        gemm64_body(g_hdec + ks * 512, kH, Wh_d + ks * 512, kH,
                    ks == 0 ? bh_d : nullptr,
                    g_ghd + (size_t)ks * kB * kG, kG, 512, 0, nb);
    }
}

// ---------------------------------------------------------------------------
__global__ void hcat_kernel() {
    int idx = blockIdx.x * blockDim.x + threadIdx.x;
    if (idx >= 2 * kB * kH) return;
    int dir = idx / (kB * kH);
    int rem = idx - dir * (kB * kH);
    int b = rem / kH, j = rem - b * kH;
    g_hcat[(size_t)b * 2 * kH + dir * kH + j] = g_h[0][idx];
}

// ---------------------------------------------------------------------------
// Fully fused decoder step (512 threads)
// ---------------------------------------------------------------------------
__global__ __launch_bounds__(512)
void attn_step_fused(const int* __restrict__ src,
                     const float* __restrict__ v_attn,
                     const float* __restrict__ gxet_t,
                     float* __restrict__ feat_t) {
    int b = blockIdx.x;
    __shared__ float sc[kS];
    __shared__ float sgxw[kG];
    int tid = threadIdx.x, warp = tid >> 5, lane = tid & 31;
    const float* hp0 = g_hp + (size_t)b * kH;
    const float* hp1 = g_hp + (size_t)kB * kH + (size_t)b * kH;

    for (int s = warp; s < kS; s += 16) {
        const float* ep = g_encproj + ((size_t)b * kS + s) * kH;
        float p = 0.f;
        for (int j = lane; j < kH; j += 32)
            p += v_attn[j] * tanhf(hp0[j] + hp1[j] + ep[j]);
#pragma unroll
        for (int o = 16; o; o >>= 1) p += __shfl_xor_sync(0xffffffffu, p, o);
        if (lane == 0) sc[s] = (src[s * kB + b] != kPAD) ? p : -1e10f;
    }
    __syncthreads();

    if (tid < 32) {
        float v1 = sc[tid];
        float v2 = (tid + 32 < kS) ? sc[tid + 32] : -1e30f;
        float mx = fmaxf(v1, v2);
#pragma unroll
        for (int o = 16; o; o >>= 1) mx = fmaxf(mx, __shfl_xor_sync(0xffffffffu, mx, o));
        float e1 = expf(v1 - mx);
        float e2 = (tid + 32 < kS) ? expf(v2 - mx) : 0.f;
        float sm = e1 + e2;
#pragma unroll
        for (int o = 16; o; o >>= 1) sm += __shfl_xor_sync(0xffffffffu, sm, o);
        float inv = 1.f / sm;
        sc[tid] = e1 * inv;
        if (tid + 32 < kS) sc[tid + 32] = e2 * inv;
    }
    __syncthreads();

    for (int c4 = tid; c4 < 2 * kH / 4; c4 += 512) {
        float4 acc = make_float4(0.f, 0.f, 0.f, 0.f);
        const float4* base = (const float4*)(g_enc + (size_t)b * kS * 2 * kH) + c4;
#pragma unroll 8
        for (int s = 0; s < kS; s++) {
            float a = sc[s];
            float4 e = base[s * (2 * kH / 4)];
            acc.x += a * e.x; acc.y += a * e.y;
            acc.z += a * e.z; acc.w += a * e.w;
        }
        ((float4*)(feat_t + (size_t)b * kF + kH))[c4] = acc;
    }
    for (int c4 = tid; c4 < kG / 4; c4 += 512) {
        float4 acc = make_float4(0.f, 0.f, 0.f, 0.f);
        const float4* base = (const float4*)(g_encWi + (size_t)b * kS * kG) + c4;
#pragma unroll 8
        for (int s = 0; s < kS; s++) {
            float a = sc[s];
            float4 e = base[s * (kG / 4)];
            acc.x += a * e.x; acc.y += a * e.y;
            acc.z += a * e.z; acc.w += a * e.w;
        }
        *(float4*)(sgxw + c4 * 4) = acc;
    }
    __syncthreads();

    const float* q0 = g_ghd + (size_t)b * kG;
    const float* q1 = g_ghd + (size_t)kB * kG + (size_t)b * kG;
    const float* gx = gxet_t + (size_t)b * kG;
    for (int j = tid; j < kH; j += 512) {
        float h = g_hdec[(size_t)b * kH + j];
        float xr = gx[j] + sgxw[j];
        float xz = gx[kH + j] + sgxw[kH + j];
        float xn = gx[2 * kH + j] + sgxw[2 * kH + j];
        float ghr = q0[j] + q1[j];
        float ghz = q0[kH + j] + q1[kH + j];
        float ghn = q0[2 * kH + j] + q1[2 * kH + j];
        float r = 1.f / (1.f + expf(-(xr + ghr)));
        float z = 1.f / (1.f + expf(-(xz + ghz)));
        float n = tanhf(xn + r * ghn);
        float h2 = (1.f - z) * n + z * h;
        g_hdec[(size_t)b * kH + j] = h2;
        feat_t[(size_t)b * kF + j] = h2;
    }
}

// ---------------------------------------------------------------------------
// Host orchestration (two-stream fork/join, graph-capturable)
// ---------------------------------------------------------------------------
extern "C" void kernel_launch(void* const* d_in, const int* in_sizes, int n_in,
                              void* d_out, int out_size) {
    const int*   src     = (const int*)d_in[0];
    const int*   trg     = (const int*)d_in[1];
    const float* emb_enc = (const float*)d_in[2];
    const float* Wi_f    = (const float*)d_in[3];
    const float* Wh_f    = (const float*)d_in[4];
    const float* bi_f    = (const float*)d_in[5];
    const float* bh_f    = (const float*)d_in[6];
    const float* Wi_b    = (const float*)d_in[7];
    const float* Wh_b    = (const float*)d_in[8];
    const float* bi_b    = (const float*)d_in[9];
    const float* bh_b    = (const float*)d_in[10];
    const float* W_fc    = (const float*)d_in[11];
    const float* b_fc    = (const float*)d_in[12];
    const float* W_attn  = (const float*)d_in[13];
    const float* b_attn  = (const float*)d_in[14];
    const float* v_attn  = (const float*)d_in[15];
    const float* emb_dec = (const float*)d_in[16];
    const float* Wi_d    = (const float*)d_in[17];
    const float* Wh_d    = (const float*)d_in[18];
    const float* bi_d    = (const float*)d_in[19];
    const float* bh_d    = (const float*)d_in[20];
    const float* W_out   = (const float*)d_in[21];
    const float* b_out   = (const float*)d_in[22];
    float* out = (float*)d_out;

    float *p_enc, *p_ep, *p_encWi, *p_hcat, *p_hdec, *p_gxet, *p_feat,
          *p_gxf, *p_gxb;
    __nv_bfloat16 *p_Ahi, *p_Alo, *p_Bhi, *p_Blo, *p_Ehi, *p_Elo;
    __nv_bfloat16 *p_Wifh, *p_Wifl, *p_Wibh, *p_Wibl;
    __nv_bfloat16 *p_Widh, *p_Widl, *p_Wah, *p_Wal, *p_Ench, *p_Encl;
    cudaGetSymbolAddress((void**)&p_enc, g_enc);
    cudaGetSymbolAddress((void**)&p_ep, g_encproj);
    cudaGetSymbolAddress((void**)&p_encWi, g_encWi);
    cudaGetSymbolAddress((void**)&p_hcat, g_hcat);
    cudaGetSymbolAddress((void**)&p_hdec, g_hdec);
    cudaGetSymbolAddress((void**)&p_gxet, g_gxet);
    cudaGetSymbolAddress((void**)&p_feat, g_feat);
    cudaGetSymbolAddress((void**)&p_gxf, g_gxf);
    cudaGetSymbolAddress((void**)&p_gxb, g_gxb);
    cudaGetSymbolAddress((void**)&p_Ahi, g_Ahi);
    cudaGetSymbolAddress((void**)&p_Alo, g_Alo);
    cudaGetSymbolAddress((void**)&p_Bhi, g_Bhi);
    cudaGetSymbolAddress((void**)&p_Blo, g_Blo);
    cudaGetSymbolAddress((void**)&p_Ehi, g_Ehi);
    cudaGetSymbolAddress((void**)&p_Elo, g_Elo);
    cudaGetSymbolAddress((void**)&p_Wifh, g_Wifh);
    cudaGetSymbolAddress((void**)&p_Wifl, g_Wifl);
    cudaGetSymbolAddress((void**)&p_Wibh, g_Wibh);
    cudaGetSymbolAddress((void**)&p_Wibl, g_Wibl);
    cudaGetSymbolAddress((void**)&p_Widh, g_Widh);
    cudaGetSymbolAddress((void**)&p_Widl, g_Widl);
    cudaGetSymbolAddress((void**)&p_Wah, g_Wah);
    cudaGetSymbolAddress((void**)&p_Wal, g_Wal);
    cudaGetSymbolAddress((void**)&p_Ench, g_Ench);
    cudaGetSymbolAddress((void**)&p_Encl, g_Encl);

    static cudaStream_t s1 = nullptr;
    static cudaEvent_t evFork = nullptr, evJoin = nullptr;
    if (s1 == nullptr) {
        cudaStreamCreateWithFlags(&s1, cudaStreamNonBlocking);
        cudaEventCreateWithFlags(&evFork, cudaEventDisableTiming);
        cudaEventCreateWithFlags(&evJoin, cudaEventDisableTiming);
        cudaFuncSetAttribute(hgemm,
                             cudaFuncAttributeMaxDynamicSharedMemorySize,
                             outg::SMEM_SZ);
    }

    // fork side stream off the capture stream
    cudaEventRecord(evFork, 0);
    cudaStreamWaitEvent(s1, evFork, 0);

    // --- main stream: encoder-critical path ---
    init_kernel<<<((size_t)kB * kV + 255) / 256, 256>>>(out);
    enc_embed_kernel<<<kME, 128>>>(src, emb_enc);
    {
        size_t n4 = (size_t)kG * kE / 4;
        cvt_split4<<<(unsigned)((n4 + 255) / 256), 256>>>(
            (const float4*)Wi_f, (__nv_bfloat162*)p_Wifh,
            (__nv_bfloat162*)p_Wifl, n4);
        cvt_split4<<<(unsigned)((n4 + 255) / 256), 256>>>(
            (const float4*)Wi_b, (__nv_bfloat162*)p_Wibh,
            (__nv_bfloat162*)p_Wibl, n4);
    }
    // --- side stream: decoder-prep + big weight conversions ---
    dec_embed_all<<<kMR, 128, 0, s1>>>(trg, emb_dec);
    // --- main: input-gate GEMMs ---
    hgemm<<<dim3(kME / 128, kG / 128), 256, outg::SMEM_SZ>>>(
        p_Ehi, p_Elo, kE, p_Wifh, p_Wifl, kE, bi_f, p_gxf, kG, kME, kE);
    hgemm<<<dim3(kME / 128, kG / 128), 256, outg::SMEM_SZ>>>(
        p_Ehi, p_Elo, kE, p_Wibh, p_Wibl, kE, bi_b, p_gxb, kG, kME, kE);
    // --- side stream continues ---
    {
        size_t n4 = (size_t)kG * kXW / 4;
        cvt_split4<<<(unsigned)((n4 + 255) / 256), 256, 0, s1>>>(
            (const float4*)Wi_d, (__nv_bfloat162*)p_Widh,
            (__nv_bfloat162*)p_Widl, n4);
        n4 = (size_t)kH * kG / 4;
        cvt_split4<<<(unsigned)((n4 + 255) / 256), 256, 0, s1>>>(
            (const float4*)W_attn, (__nv_bfloat162*)p_Wah,
            (__nv_bfloat162*)p_Wal, n4);
        hgemm<<<dim3(kMP / 128, kG / 128), 256, outg::SMEM_SZ, s1>>>(
            p_Ahi + 3 * kH, p_Alo + 3 * kH, kF, p_Widh, p_Widl, kXW, bi_d,
            p_gxet, kG, kMR, kE);
        n4 = (size_t)kV * kF / 4;
        cvt_split4<<<(unsigned)((n4 + 255) / 256), 256, 0, s1>>>(
            (const float4*)W_out, (__nv_bfloat162*)p_Bhi,
            (__nv_bfloat162*)p_Blo, n4);
    }
    cudaEventRecord(evJoin, s1);

    // --- main: encoder recurrence (overlaps side stream) ---
    for (int s = 0; s < kS; s++)
        enc_step_fused<<<dim3(64, 2), 256>>>(s, Wh_f, Wh_b, bh_f, bh_b);

    // decoder init hidden
    hcat_kernel<<<(2 * kB * kH) / 256, 256>>>();
    gemm64<<<kH / 64, 256>>>(p_hcat, 2 * kH, W_fc, 2 * kH, b_fc,
                             p_hdec, kH, 2 * kH, 1);

    // encoder split + attention projection + encWi (needs side stream)
    {
        size_t n4 = (size_t)kME * 2 * kH / 4;
        cvt_split4<<<(unsigned)((n4 + 255) / 256), 256>>>(
            (const float4*)p_enc, (__nv_bfloat162*)p_Ench,
            (__nv_bfloat162*)p_Encl, n4);
        cudaStreamWaitEvent(0, evJoin, 0);
        hgemm<<<dim3(kME / 128, kH / 128), 256, outg::SMEM_SZ>>>(
            p_Ench, p_Encl, 2 * kH, p_Wah + kH, p_Wal + kH, kG, b_attn,
            p_ep, kH, kME, 2 * kH);
        hgemm<<<dim3(kME / 128, kG / 128), 256, outg::SMEM_SZ>>>(
            p_Ench, p_Encl, 2 * kH, p_Widh + kE, p_Widl + kE, kXW,
            (const float*)nullptr, p_encWi, kG, kME, 2 * kH);
    }

    // decoder loop: 2 launches per step (keep L2 decoder-owned; no overlap)
    for (int t = 0; t < kT - 1; t++) {
        float* feat_t = p_feat + (size_t)t * kB * kF;
        dec_pre_gemm<<<128, 256>>>(W_attn, Wh_d, bh_d);
        attn_step_fused<<<kB, 512>>>(src, v_attn,
                                     p_gxet + (size_t)t * kB * kG, feat_t);
    }

    // split-convert features, single full HMMA output projection
    {
        size_t n = (size_t)kMP * (3 * kH) / 4;
        cvt_feat_split<<<(unsigned)((n + 255) / 256), 256>>>();
        hgemm<<<dim3(kMP / 128, kV / 128), 256, outg::SMEM_SZ>>>(
            p_Ahi, p_Alo, kF, p_Bhi, p_Blo, kF, b_out,
            out + (size_t)kB * kV, kV, kMR, kF);
    }
}